// round 10
// baseline (speedup 1.0000x reference)
#include <cuda_runtime.h>
#include <cuda_bf16.h>
#include <cstdint>

// ---------------------------------------------------------------------------
// CompressedGNN on GB300 (plain sm_103 target).
// GEMMs: HMMA bf16 split x3 fused; operands in k-chunk-major layout, loaded
// with cp.async.bulk (4 ops/iter instead of 1024 LDGSTS) + mbarrier.
// Aggregation: CSR gather (atomic-free), fused bf16 hi/lo split output.
// ---------------------------------------------------------------------------

#define NNODES 10000
#define MAXE   160000
#define DH     512
#define NPADC  128
#define NCH    (DH / 16)          // 32 k-chunks of 16

// fp32 GEMM output (consumed by aggregation)
__device__ float g_h[NNODES * DH];
// k-chunk-major split operands: [chunk][row][16] bf16, 16B-chunk permuted.
// +256 uint4 slack rows so the last m-block's bulk read stays in bounds.
__device__ uint4 g_ahi[NCH * NNODES * 2 + 256];
__device__ uint4 g_alo[NCH * NNODES * 2 + 256];
__device__ uint4 g_w1hi[NCH * DH * 2];
__device__ uint4 g_w1lo[NCH * DH * 2];
__device__ uint4 g_w2hi[NCH * DH * 2];
__device__ uint4 g_w2lo[NCH * DH * 2];
__device__ uint4 g_wchi[NCH * NPADC * 2];
__device__ uint4 g_wclo[NCH * NPADC * 2];
__device__ float g_dinv[NNODES];
__device__ int   g_cnt[NNODES];
__device__ int   g_rowptr[NNODES + 1];
__device__ int   g_cursor[NNODES];
__device__ int   g_col[MAXE];

// ---------------------------------------------------------------------------
__device__ __forceinline__ uint32_t smem_to_u32(const void* p) {
    uint32_t a;
    asm("{ .reg .u64 t; cvta.to.shared.u64 t, %1; cvt.u32.u64 %0, t; }"
        : "=r"(a) : "l"(p));
    return a;
}

__device__ __forceinline__ void ldmat_x4(uint32_t (&r)[4], uint32_t addr) {
    asm volatile("ldmatrix.sync.aligned.m8n8.x4.shared.b16 {%0,%1,%2,%3}, [%4];"
                 : "=r"(r[0]), "=r"(r[1]), "=r"(r[2]), "=r"(r[3]) : "r"(addr));
}

__device__ __forceinline__ void mma_bf16(float (&d)[4], const uint32_t (&a)[4],
                                         uint32_t b0, uint32_t b1) {
    asm volatile("mma.sync.aligned.m16n8k16.row.col.f32.bf16.bf16.f32 "
                 "{%0,%1,%2,%3}, {%4,%5,%6,%7}, {%8,%9}, {%0,%1,%2,%3};"
                 : "+f"(d[0]), "+f"(d[1]), "+f"(d[2]), "+f"(d[3])
                 : "r"(a[0]), "r"(a[1]), "r"(a[2]), "r"(a[3]), "r"(b0), "r"(b1));
}

__device__ __forceinline__ void bulk_cp(uint32_t dst, const void* src,
                                        uint32_t bytes, uint32_t mbar) {
    asm volatile(
        "cp.async.bulk.shared::cta.global.mbarrier::complete_tx::bytes "
        "[%0], [%1], %2, [%3];"
        :: "r"(dst), "l"(src), "r"(bytes), "r"(mbar) : "memory");
}

#define MBARRIER_INIT(addr, cnt) \
    asm volatile("mbarrier.init.shared.b64 [%0], %1;" \
                 :: "r"((uint32_t)(addr)), "r"((uint32_t)(cnt)) : "memory")
#define MBARRIER_EXPECT_TX(addr, bytes) \
    asm volatile("mbarrier.arrive.expect_tx.shared.b64 _, [%0], %1;" \
                 :: "r"((uint32_t)(addr)), "r"((uint32_t)(bytes)) : "memory")
#define MBARRIER_WAIT_PARITY(addr, par) do { \
    uint32_t _m = (uint32_t)(addr); uint32_t _p = (uint32_t)(par); uint32_t _d; \
    asm volatile("{\n\t.reg .pred p;\n\t" \
        "mbarrier.try_wait.parity.acquire.cta.shared::cta.b64 p, [%1], %2;\n\t" \
        "selp.b32 %0, 1, 0, p;\n\t}" : "=r"(_d) : "r"(_m), "r"(_p) : "memory"); \
    if (!_d) { \
        asm volatile("{\n\t.reg .pred P1;\n\t" \
            "WL_%=:\n\t" \
            "mbarrier.try_wait.parity.acquire.cta.shared::cta.b64 P1, [%0], %1, 0x989680;\n\t" \
            "@P1 bra.uni WD_%=;\n\t" \
            "bra.uni WL_%=;\n\t" \
            "WD_%=:\n\t}" :: "r"(_m), "r"(_p) : "memory"); \
    } \
} while (0)

// ---------------------------------------------------------------------------
// CSR build
// ---------------------------------------------------------------------------
__global__ void zero_cnt_kernel(int n) {
    int i = blockIdx.x * blockDim.x + threadIdx.x;
    if (i < n) g_cnt[i] = 0;
}

__global__ void count_kernel(const int* __restrict__ ei, int E, int n) {
    int e = blockIdx.x * blockDim.x + threadIdx.x;
    if (e < E) {
        int d = ei[E + e];
        if (d >= 0 && d < n) atomicAdd(&g_cnt[d], 1);
    }
}

__global__ void scan_kernel(int n) {
    __shared__ int part[1024];
    int tid = threadIdx.x;
    int CH = (n + 1023) / 1024;
    int base = tid * CH;
    int s = 0;
    for (int i = 0; i < CH; ++i) {
        int idx = base + i;
        if (idx < n) s += g_cnt[idx];
    }
    part[tid] = s;
    __syncthreads();
    for (int off = 1; off < 1024; off <<= 1) {
        int add = (tid >= off) ? part[tid - off] : 0;
        __syncthreads();
        part[tid] += add;
        __syncthreads();
    }
    int run = part[tid] - s;
    for (int i = 0; i < CH; ++i) {
        int idx = base + i;
        if (idx < n) {
            g_rowptr[idx] = run;
            g_cursor[idx] = run;
            int c = g_cnt[idx];
            g_dinv[idx] = rsqrtf(1.0f + (float)c);
            run += c;
        }
    }
    if (tid == 0) g_rowptr[n] = part[1023];
}

__global__ void fill_kernel(const int* __restrict__ ei, int E, int n) {
    int e = blockIdx.x * blockDim.x + threadIdx.x;
    if (e < E) {
        int s = ei[e];
        int d = ei[E + e];
        if (d >= 0 && d < n && s >= 0 && s < n) {
            int pos = atomicAdd(&g_cursor[d], 1);
            g_col[pos] = s;
        }
    }
}

// ---------------------------------------------------------------------------
// bf16 split prep (k-chunk-major, 16B-chunk permuted)
// ---------------------------------------------------------------------------
__device__ __forceinline__ void split_bf16(float v, __nv_bfloat16& hi, __nv_bfloat16& lo) {
    hi = __float2bfloat16(v);
    lo = __float2bfloat16(v - __bfloat162float(hi));
}

// one thread per (row, kchunk): reads 16 floats, writes 2x16B to hi and lo.
__global__ void conv_x_kernel(const float* __restrict__ x) {
    int idx = blockIdx.x * blockDim.x + threadIdx.x;
    if (idx >= NNODES * NCH) return;
    int c = idx & (NCH - 1);
    int row = idx >> 5;
    const float4* xr = (const float4*)(x + (size_t)row * DH + c * 16);
    float v[16];
#pragma unroll
    for (int q = 0; q < 4; ++q) {
        float4 t = xr[q];
        v[q * 4 + 0] = t.x; v[q * 4 + 1] = t.y; v[q * 4 + 2] = t.z; v[q * 4 + 3] = t.w;
    }
    __nv_bfloat16 hi[16], lo[16];
#pragma unroll
    for (int q = 0; q < 16; ++q) split_bf16(v[q], hi[q], lo[q]);
    int f = (row >> 2) & 1;
    size_t base = ((size_t)c * NNODES + row) * 2;
#pragma unroll
    for (int j = 0; j < 2; ++j) {
        g_ahi[base + (j ^ f)] = *(uint4*)(hi + j * 8);
        g_alo[base + (j ^ f)] = *(uint4*)(lo + j * 8);
    }
}

// Transpose + split: W [DH x N] -> chunk-major [kchunk][ldn][16]. which: 0/1/2.
__global__ void prep_w_kernel(const float* __restrict__ W, int N, int ldn, int which) {
    __shared__ float t[32][33];
    int k0 = blockIdx.x * 32, n0 = blockIdx.y * 32;
    int tx = threadIdx.x, ty = threadIdx.y;
    int k = k0 + ty, n = n0 + tx;
    float v = 0.0f;
    if (n < N) v = W[(size_t)k * N + n];
    t[ty][tx] = v;
    __syncthreads();
    int on = n0 + ty, ok = k0 + tx;
    float w = t[tx][ty];
    __nv_bfloat16 hi, lo;
    split_bf16(w, hi, lo);
    __nv_bfloat16 *dh, *dl;
    if (which == 0)      { dh = (__nv_bfloat16*)g_w1hi; dl = (__nv_bfloat16*)g_w1lo; }
    else if (which == 1) { dh = (__nv_bfloat16*)g_w2hi; dl = (__nv_bfloat16*)g_w2lo; }
    else                 { dh = (__nv_bfloat16*)g_wchi; dl = (__nv_bfloat16*)g_wclo; }
    int c = ok >> 4, jj = (ok >> 3) & 1, pos = ok & 7;
    int f = (on >> 2) & 1;
    size_t bfidx = (((size_t)c * ldn + on) * 2 + (jj ^ f)) * 8 + pos;
    dh[bfidx] = hi;
    dl[bfidx] = lo;
}

// ---------------------------------------------------------------------------
// HMMA GEMM, bulk-copy pipelined. 128x128 CTA tile, BK=16, 8 warps (2x4).
// ---------------------------------------------------------------------------
#define BMt 128
#define BNt 128
#define TILEB 4096                 // 128 rows x 32B
#define STAGEB (4 * TILEB)         // Ahi|Alo|Bhi|Blo

__global__ __launch_bounds__(256, 2)
void mma_gemm_kernel(int which, const float* __restrict__ bias,
                     float* __restrict__ extout, int Nvalid)
{
    __shared__ __align__(128) char sMem[2 * STAGEB];   // 32768 B
    __shared__ __align__(16) uint64_t sBar[2];

    int tid = threadIdx.x, lane = tid & 31, wid = tid >> 5;
    int m0 = blockIdx.y * BMt, n0 = blockIdx.x * BNt;
    int warp_m = (wid >> 2) * 64, warp_n = (wid & 3) * 32;
    int ldn = (which == 2) ? NPADC : DH;

    const uint4 *Wh, *Wl;
    if (which == 0)      { Wh = g_w1hi; Wl = g_w1lo; }
    else if (which == 1) { Wh = g_w2hi; Wl = g_w2lo; }
    else                 { Wh = g_wchi; Wl = g_wclo; }

    uint32_t base = smem_to_u32(sMem);
    uint32_t bar0 = smem_to_u32(&sBar[0]);
    uint32_t bar1 = smem_to_u32(&sBar[1]);

    if (tid == 0) {
        MBARRIER_INIT(bar0, 1);
        MBARRIER_INIT(bar1, 1);
    }
    __syncthreads();

    float acc[4][4][4];
#pragma unroll
    for (int a = 0; a < 4; ++a)
#pragma unroll
        for (int b = 0; b < 4; ++b)
#pragma unroll
            for (int c = 0; c < 4; ++c) acc[a][b][c] = 0.0f;

#define ISSUE(it, buf) do {                                                    \
        uint32_t _bar = (buf) ? bar1 : bar0;                                   \
        uint32_t _d = base + (buf) * STAGEB;                                   \
        MBARRIER_EXPECT_TX(_bar, 4 * TILEB);                                   \
        bulk_cp(_d,             (const char*)g_ahi + ((size_t)(it) * NNODES + m0) * 32, TILEB, _bar); \
        bulk_cp(_d + TILEB,     (const char*)g_alo + ((size_t)(it) * NNODES + m0) * 32, TILEB, _bar); \
        bulk_cp(_d + 2 * TILEB, (const char*)Wh    + ((size_t)(it) * ldn + n0) * 32,    TILEB, _bar); \
        bulk_cp(_d + 3 * TILEB, (const char*)Wl    + ((size_t)(it) * ldn + n0) * 32,    TILEB, _bar); \
    } while (0)

    if (tid == 0) ISSUE(0, 0);

    // fragment smem offsets (constant across iterations)
    uint32_t aFragOff[4], bFragOff[2];
#pragma unroll
    for (int mf = 0; mf < 4; ++mf) {
        int row = warp_m + mf * 16 + (lane & 15);
        int cs = (lane >> 4) ^ ((row >> 2) & 1);
        aFragOff[mf] = (uint32_t)(row * 32 + cs * 16);
    }
#pragma unroll
    for (int nb = 0; nb < 2; ++nb) {
        int nrow = warp_n + nb * 16 + ((lane >> 4) << 3) + (lane & 7);
        int cs = ((lane >> 3) & 1) ^ ((nrow >> 2) & 1);
        bFragOff[nb] = (uint32_t)(nrow * 32 + cs * 16);
    }

    for (int it = 0; it < NCH; ++it) {
        int buf = it & 1;
        if (tid == 0 && it + 1 < NCH) ISSUE(it + 1, buf ^ 1);
        MBARRIER_WAIT_PARITY(buf ? bar1 : bar0, (it >> 1) & 1);

        uint32_t sb = base + buf * STAGEB;
        uint32_t ahi[4][4], bhi[2][4], blo[2][4];
#pragma unroll
        for (int mf = 0; mf < 4; ++mf) ldmat_x4(ahi[mf], sb + aFragOff[mf]);
#pragma unroll
        for (int nb = 0; nb < 2; ++nb) {
            ldmat_x4(bhi[nb], sb + 2 * TILEB + bFragOff[nb]);
            ldmat_x4(blo[nb], sb + 3 * TILEB + bFragOff[nb]);
        }
        // HH
#pragma unroll
        for (int mf = 0; mf < 4; ++mf)
#pragma unroll
            for (int nf = 0; nf < 4; ++nf)
                mma_bf16(acc[mf][nf], ahi[mf],
                         bhi[nf >> 1][(nf & 1) * 2], bhi[nf >> 1][(nf & 1) * 2 + 1]);
        // HL
#pragma unroll
        for (int mf = 0; mf < 4; ++mf)
#pragma unroll
            for (int nf = 0; nf < 4; ++nf)
                mma_bf16(acc[mf][nf], ahi[mf],
                         blo[nf >> 1][(nf & 1) * 2], blo[nf >> 1][(nf & 1) * 2 + 1]);
        // LH
        uint32_t alo[4][4];
#pragma unroll
        for (int mf = 0; mf < 4; ++mf) ldmat_x4(alo[mf], sb + TILEB + aFragOff[mf]);
#pragma unroll
        for (int mf = 0; mf < 4; ++mf)
#pragma unroll
            for (int nf = 0; nf < 4; ++nf)
                mma_bf16(acc[mf][nf], alo[mf],
                         bhi[nf >> 1][(nf & 1) * 2], bhi[nf >> 1][(nf & 1) * 2 + 1]);
        __syncthreads();
    }
#undef ISSUE

    // epilogue
#pragma unroll
    for (int mf = 0; mf < 4; ++mf) {
        int rr = m0 + warp_m + mf * 16 + (lane >> 2);
#pragma unroll
        for (int nf = 0; nf < 4; ++nf) {
            int cc = n0 + warp_n + nf * 8 + (lane & 3) * 2;
            float d0 = acc[mf][nf][0], d1 = acc[mf][nf][1];
            float d2 = acc[mf][nf][2], d3 = acc[mf][nf][3];
            if (extout) {
                if (rr < NNODES) {
                    if (cc < Nvalid)     extout[(size_t)rr * Nvalid + cc]     = d0 + bias[cc];
                    if (cc + 1 < Nvalid) extout[(size_t)rr * Nvalid + cc + 1] = d1 + bias[cc + 1];
                }
                if (rr + 8 < NNODES) {
                    if (cc < Nvalid)     extout[(size_t)(rr + 8) * Nvalid + cc]     = d2 + bias[cc];
                    if (cc + 1 < Nvalid) extout[(size_t)(rr + 8) * Nvalid + cc + 1] = d3 + bias[cc + 1];
                }
            } else {
                if (rr < NNODES)     *(float2*)&g_h[(size_t)rr * DH + cc]       = make_float2(d0, d1);
                if (rr + 8 < NNODES) *(float2*)&g_h[(size_t)(rr + 8) * DH + cc] = make_float2(d2, d3);
            }
        }
    }
}

// ---------------------------------------------------------------------------
// Aggregation: one block per node; writes chunk-major split bf16 for next GEMM.
// ---------------------------------------------------------------------------
__global__ __launch_bounds__(128) void agg_kernel(
    const float* __restrict__ bias, int relu)
{
    int i = blockIdx.x;
    int tid = threadIdx.x;
    const float4* h4 = (const float4*)g_h;
    float di = g_dinv[i];
    int beg = g_rowptr[i];
    int end = g_rowptr[i + 1];

    float4 acc = make_float4(0.f, 0.f, 0.f, 0.f);
#pragma unroll 2
    for (int jj = beg; jj < end; ++jj) {
        int s = g_col[jj];
        float w = g_dinv[s] * di;
        float4 v = h4[(size_t)s * (DH / 4) + tid];
        acc.x += v.x * w;
        acc.y += v.y * w;
        acc.z += v.z * w;
        acc.w += v.w * w;
    }
    float sw = di * di;
    float4 self = h4[(size_t)i * (DH / 4) + tid];
    acc.x += self.x * sw;
    acc.y += self.y * sw;
    acc.z += self.z * sw;
    acc.w += self.w * sw;
    const float4* b4 = (const float4*)bias;
    float4 bb = b4[tid];
    acc.x += bb.x; acc.y += bb.y; acc.z += bb.z; acc.w += bb.w;
    if (relu) {
        acc.x = fmaxf(acc.x, 0.f);
        acc.y = fmaxf(acc.y, 0.f);
        acc.z = fmaxf(acc.z, 0.f);
        acc.w = fmaxf(acc.w, 0.f);
    }
    float v[4] = {acc.x, acc.y, acc.z, acc.w};
    __nv_bfloat16 hi[4], lo[4];
#pragma unroll
    for (int jj = 0; jj < 4; ++jj) split_bf16(v[jj], hi[jj], lo[jj]);
    // chunk-major dst: cols 4t..4t+3 -> chunk c=t>>2, 16B-sub j=(t>>1)&1, half t&1
    int c = tid >> 2;
    int j = (tid >> 1) & 1;
    int f = (i >> 2) & 1;
    size_t chunk16 = ((size_t)c * NNODES + i) * 2 + (j ^ f);
    ((uint2*)g_ahi)[chunk16 * 2 + (tid & 1)] = *(uint2*)hi;
    ((uint2*)g_alo)[chunk16 * 2 + (tid & 1)] = *(uint2*)lo;
}

// ---------------------------------------------------------------------------
extern "C" void kernel_launch(void* const* d_in, const int* in_sizes, int n_in,
                              void* d_out, int out_size) {
    const float* x  = (const float*)d_in[0];
    const int*   ei = (const int*)d_in[1];     // int32 (JAX x64 disabled)
    const float* W1 = (const float*)d_in[2];
    const float* b1 = (const float*)d_in[3];
    const float* W2 = (const float*)d_in[4];
    const float* b2 = (const float*)d_in[5];
    const float* Wc = (const float*)d_in[6];
    const float* bc = (const float*)d_in[7];
    float* out = (float*)d_out;

    int N = in_sizes[0] / DH;             // 10000
    int E = in_sizes[1] / 2;              // 160000
    int d_out_dim = in_sizes[6] / DH;     // 100

    // CSR build
    zero_cnt_kernel<<<(N + 255) / 256, 256>>>(N);
    count_kernel<<<(E + 255) / 256, 256>>>(ei, E, N);
    scan_kernel<<<1, 1024>>>(N);
    fill_kernel<<<(E + 255) / 256, 256>>>(ei, E, N);

    // operand prep (chunk-major split)
    conv_x_kernel<<<(N * NCH + 255) / 256, 256>>>(x);
    dim3 tb(32, 32);
    prep_w_kernel<<<dim3(DH / 32, DH / 32), tb>>>(W1, DH, DH, 0);
    prep_w_kernel<<<dim3(DH / 32, DH / 32), tb>>>(W2, DH, DH, 1);
    prep_w_kernel<<<dim3(DH / 32, NPADC / 32), tb>>>(Wc, d_out_dim, NPADC, 2);

    int mblocks = (N + BMt - 1) / BMt;    // 79

    // Layer 1
    mma_gemm_kernel<<<dim3(DH / BNt, mblocks), 256>>>(0, nullptr, nullptr, DH);
    agg_kernel<<<N, 128>>>(b1, 1);

    // Layer 2
    mma_gemm_kernel<<<dim3(DH / BNt, mblocks), 256>>>(1, nullptr, nullptr, DH);
    agg_kernel<<<N, 128>>>(b2, 0);

    // Classifier
    mma_gemm_kernel<<<dim3(1, mblocks), 256>>>(2, bc, out, d_out_dim);
}

// round 11
// speedup vs baseline: 1.5565x; 1.5565x over previous
#include <cuda_runtime.h>
#include <cuda_bf16.h>
#include <cstdint>

// ---------------------------------------------------------------------------
// CompressedGNN on GB300 (plain sm_103 target — no tcgen05 in harness PTX).
// GEMMs: mma.sync bf16 (HMMA), split-precision x3 FUSED into one k-loop.
// 3-stage cp.async pipeline, permuted 32B smem rows (conflict-free ldmatrix).
// Aggregation: CSR gather (atomic-free), fused bf16 hi/lo split output.
// ---------------------------------------------------------------------------

#define NNODES 10000
#define MAXE   160000
#define DH     512
#define NPADC  128

__device__ float g_h[NNODES * DH];              // fp32 GEMM output
__device__ uint4 g_ahi[NNODES * DH / 8];        // split A operand (8 bf16/uint4)
__device__ uint4 g_alo[NNODES * DH / 8];
__device__ uint4 g_w1hi[DH * DH / 8];           // transposed split weights [N][K]
__device__ uint4 g_w1lo[DH * DH / 8];
__device__ uint4 g_w2hi[DH * DH / 8];
__device__ uint4 g_w2lo[DH * DH / 8];
__device__ uint4 g_wchi[NPADC * DH / 8];
__device__ uint4 g_wclo[NPADC * DH / 8];
__device__ float g_dinv[NNODES];
__device__ int   g_cnt[NNODES];
__device__ int   g_rowptr[NNODES + 1];
__device__ int   g_cursor[NNODES];
__device__ int   g_col[MAXE];

// ---------------------------------------------------------------------------
__device__ __forceinline__ uint32_t smem_to_u32(const void* p) {
    uint32_t a;
    asm("{ .reg .u64 t; cvta.to.shared.u64 t, %1; cvt.u32.u64 %0, t; }"
        : "=r"(a) : "l"(p));
    return a;
}

__device__ __forceinline__ void ldmat_x4(uint32_t (&r)[4], uint32_t addr) {
    asm volatile("ldmatrix.sync.aligned.m8n8.x4.shared.b16 {%0,%1,%2,%3}, [%4];"
                 : "=r"(r[0]), "=r"(r[1]), "=r"(r[2]), "=r"(r[3]) : "r"(addr));
}

__device__ __forceinline__ void mma_bf16(float (&d)[4], const uint32_t (&a)[4],
                                         uint32_t b0, uint32_t b1) {
    asm volatile("mma.sync.aligned.m16n8k16.row.col.f32.bf16.bf16.f32 "
                 "{%0,%1,%2,%3}, {%4,%5,%6,%7}, {%8,%9}, {%0,%1,%2,%3};"
                 : "+f"(d[0]), "+f"(d[1]), "+f"(d[2]), "+f"(d[3])
                 : "r"(a[0]), "r"(a[1]), "r"(a[2]), "r"(a[3]), "r"(b0), "r"(b1));
}

__device__ __forceinline__ void cp16(uint32_t dst, const void* src, bool valid) {
    int sz = valid ? 16 : 0;
    asm volatile("cp.async.cg.shared.global [%0], [%1], 16, %2;"
                 :: "r"(dst), "l"(src), "r"(sz) : "memory");
}
#define CP_COMMIT() asm volatile("cp.async.commit_group;" ::: "memory")
#define CP_WAIT0()  asm volatile("cp.async.wait_group 0;" ::: "memory")
#define CP_WAIT1()  asm volatile("cp.async.wait_group 1;" ::: "memory")

// ---------------------------------------------------------------------------
// CSR build
// ---------------------------------------------------------------------------
__global__ void zero_cnt_kernel(int n) {
    int i = blockIdx.x * blockDim.x + threadIdx.x;
    if (i < n) g_cnt[i] = 0;
}

__global__ void count_kernel(const int* __restrict__ ei, int E, int n) {
    int e = blockIdx.x * blockDim.x + threadIdx.x;
    if (e < E) {
        int d = ei[E + e];
        if (d >= 0 && d < n) atomicAdd(&g_cnt[d], 1);
    }
}

__global__ void scan_kernel(int n) {
    __shared__ int part[1024];
    int tid = threadIdx.x;
    int CH = (n + 1023) / 1024;
    int base = tid * CH;
    int s = 0;
    for (int i = 0; i < CH; ++i) {
        int idx = base + i;
        if (idx < n) s += g_cnt[idx];
    }
    part[tid] = s;
    __syncthreads();
    for (int off = 1; off < 1024; off <<= 1) {
        int add = (tid >= off) ? part[tid - off] : 0;
        __syncthreads();
        part[tid] += add;
        __syncthreads();
    }
    int run = part[tid] - s;
    for (int i = 0; i < CH; ++i) {
        int idx = base + i;
        if (idx < n) {
            g_rowptr[idx] = run;
            g_cursor[idx] = run;
            int c = g_cnt[idx];
            g_dinv[idx] = rsqrtf(1.0f + (float)c);
            run += c;
        }
    }
    if (tid == 0) g_rowptr[n] = part[1023];
}

__global__ void fill_kernel(const int* __restrict__ ei, int E, int n) {
    int e = blockIdx.x * blockDim.x + threadIdx.x;
    if (e < E) {
        int s = ei[e];
        int d = ei[E + e];
        if (d >= 0 && d < n && s >= 0 && s < n) {
            int pos = atomicAdd(&g_cursor[d], 1);
            g_col[pos] = s;
        }
    }
}

// ---------------------------------------------------------------------------
// bf16 split prep
// ---------------------------------------------------------------------------
__device__ __forceinline__ void split_bf16(float v, __nv_bfloat16& hi, __nv_bfloat16& lo) {
    hi = __float2bfloat16(v);
    lo = __float2bfloat16(v - __bfloat162float(hi));
}

__global__ void conv_x_kernel(const float* __restrict__ x) {
    int idx = blockIdx.x * blockDim.x + threadIdx.x;
    int total = NNODES * DH / 8;
    if (idx >= total) return;
    const float4* p = (const float4*)x;
    float4 a = p[idx * 2], b = p[idx * 2 + 1];
    float v[8] = {a.x, a.y, a.z, a.w, b.x, b.y, b.z, b.w};
    __nv_bfloat16 hi[8], lo[8];
#pragma unroll
    for (int j = 0; j < 8; ++j) split_bf16(v[j], hi[j], lo[j]);
    g_ahi[idx] = *(uint4*)hi;
    g_alo[idx] = *(uint4*)lo;
}

// Transpose + split: W [DH x N] -> [Npad x DH] bf16 hi/lo. which: 0/1/2.
__global__ void prep_w_kernel(const float* __restrict__ W, int N, int which) {
    __shared__ float t[32][33];
    int k0 = blockIdx.x * 32, n0 = blockIdx.y * 32;
    int tx = threadIdx.x, ty = threadIdx.y;
    int k = k0 + ty, n = n0 + tx;
    float v = 0.0f;
    if (n < N) v = W[(size_t)k * N + n];
    t[ty][tx] = v;
    __syncthreads();
    int on = n0 + ty, ok = k0 + tx;
    float w = t[tx][ty];
    __nv_bfloat16 hi, lo;
    split_bf16(w, hi, lo);
    __nv_bfloat16 *dh, *dl;
    if (which == 0)      { dh = (__nv_bfloat16*)g_w1hi; dl = (__nv_bfloat16*)g_w1lo; }
    else if (which == 1) { dh = (__nv_bfloat16*)g_w2hi; dl = (__nv_bfloat16*)g_w2lo; }
    else                 { dh = (__nv_bfloat16*)g_wchi; dl = (__nv_bfloat16*)g_wclo; }
    dh[(size_t)on * DH + ok] = hi;
    dl[(size_t)on * DH + ok] = lo;
}

// ---------------------------------------------------------------------------
// HMMA GEMM, fused split passes. 128x128 CTA tile, BK=16, 8 warps (2x4),
// warp tile 64x32. Per k-chunk: load Ahi/Alo/Bhi/Blo, do HH+HL+LH (48 mma).
// Smem rows: 32B, 16B-chunk permuted (chunk ^= (row>>2)&1) -> conflict-free
// for both cp.async stores and ldmatrix. 3-stage pipeline, 48KB exactly.
// ---------------------------------------------------------------------------
#define BMt 128
#define BNt 128
#define BKt 16
#define TILEB 4096                    // 128 rows x 32B
#define STAGEB (4 * TILEB)            // Ahi|Alo|Bhi|Blo = 16KB
#define NCH (DH / BKt)                // 32 k-chunks

__global__ __launch_bounds__(256, 2)
void mma_gemm_kernel(int which, const float* __restrict__ bias,
                     float* __restrict__ extout, int Nvalid)
{
    __shared__ __align__(128) char sMem[3 * STAGEB];   // 49152 B exactly

    int tid = threadIdx.x, lane = tid & 31, wid = tid >> 5;
    int m0 = blockIdx.y * BMt, n0 = blockIdx.x * BNt;
    int warp_m = (wid >> 2) * 64, warp_n = (wid & 3) * 32;

    const uint4 *Wh, *Wl;
    if (which == 0)      { Wh = g_w1hi; Wl = g_w1lo; }
    else if (which == 1) { Wh = g_w2hi; Wl = g_w2lo; }
    else                 { Wh = g_wchi; Wl = g_wclo; }

    uint32_t base = smem_to_u32(sMem);

    // loader: thread -> row r, 16B chunk j of each of the 4 tiles (permuted dst)
    int r = tid >> 1;
    int j = tid & 1;
    uint32_t dOff = (uint32_t)(r * 32 + ((j ^ ((r >> 2) & 1)) * 16));
    bool avalid = (m0 + r) < NNODES;
    size_t aRow = (size_t)(m0 + r) * (DH / 8) + j;
    size_t bRow = (size_t)(n0 + r) * (DH / 8) + j;

    float acc[4][4][4];
#pragma unroll
    for (int a = 0; a < 4; ++a)
#pragma unroll
        for (int b = 0; b < 4; ++b)
#pragma unroll
            for (int c = 0; c < 4; ++c) acc[a][b][c] = 0.0f;

#define ISSUE(it, buf) do {                                                  \
        size_t _ko = (size_t)(it) * 2;                                       \
        uint32_t _d = base + (buf) * STAGEB + dOff;                          \
        cp16(_d,             g_ahi + aRow + _ko, avalid);                    \
        cp16(_d + TILEB,     g_alo + aRow + _ko, avalid);                    \
        cp16(_d + 2 * TILEB, Wh    + bRow + _ko, true);                      \
        cp16(_d + 3 * TILEB, Wl    + bRow + _ko, true);                      \
    } while (0)

    ISSUE(0, 0);
    CP_COMMIT();
    ISSUE(1, 1);
    CP_COMMIT();

    // fragment smem offsets (constant across iterations; permuted chunks)
    uint32_t aFragOff[4], bFragOff[2];
#pragma unroll
    for (int mf = 0; mf < 4; ++mf) {
        int row = warp_m + mf * 16 + (lane & 15);
        int cs = (lane >> 4) ^ ((row >> 2) & 1);
        aFragOff[mf] = (uint32_t)(row * 32 + cs * 16);
    }
#pragma unroll
    for (int nb = 0; nb < 2; ++nb) {
        int nrow = warp_n + nb * 16 + ((lane >> 4) << 3) + (lane & 7);
        int cs = ((lane >> 3) & 1) ^ ((nrow >> 2) & 1);
        bFragOff[nb] = (uint32_t)(nrow * 32 + cs * 16);
    }

    int buf = 0;
    for (int it = 0; it < NCH; ++it) {
        // wait for stage `it`'s data
        if (it + 1 < NCH) CP_WAIT1(); else CP_WAIT0();
        __syncthreads();   // also: all warps done computing stage it-1

        // prefetch stage it+2 into buffer (it+2)%3 (free: computed at it-1)
        if (it + 2 < NCH) {
            int buf2 = buf + 2; if (buf2 >= 3) buf2 -= 3;
            ISSUE(it + 2, buf2);
            CP_COMMIT();
        }

        uint32_t sb = base + buf * STAGEB;
        uint32_t ahi[4][4], bhi[2][4], blo[2][4];
#pragma unroll
        for (int mf = 0; mf < 4; ++mf) ldmat_x4(ahi[mf], sb + aFragOff[mf]);
#pragma unroll
        for (int nb = 0; nb < 2; ++nb) {
            ldmat_x4(bhi[nb], sb + 2 * TILEB + bFragOff[nb]);
            ldmat_x4(blo[nb], sb + 3 * TILEB + bFragOff[nb]);
        }
        // HH
#pragma unroll
        for (int mf = 0; mf < 4; ++mf)
#pragma unroll
            for (int nf = 0; nf < 4; ++nf)
                mma_bf16(acc[mf][nf], ahi[mf],
                         bhi[nf >> 1][(nf & 1) * 2], bhi[nf >> 1][(nf & 1) * 2 + 1]);
        // HL
#pragma unroll
        for (int mf = 0; mf < 4; ++mf)
#pragma unroll
            for (int nf = 0; nf < 4; ++nf)
                mma_bf16(acc[mf][nf], ahi[mf],
                         blo[nf >> 1][(nf & 1) * 2], blo[nf >> 1][(nf & 1) * 2 + 1]);
        // LH (alo loaded after ahi is dead; registers can overlap)
        uint32_t alo[4][4];
#pragma unroll
        for (int mf = 0; mf < 4; ++mf) ldmat_x4(alo[mf], sb + TILEB + aFragOff[mf]);
#pragma unroll
        for (int mf = 0; mf < 4; ++mf)
#pragma unroll
            for (int nf = 0; nf < 4; ++nf)
                mma_bf16(acc[mf][nf], alo[mf],
                         bhi[nf >> 1][(nf & 1) * 2], bhi[nf >> 1][(nf & 1) * 2 + 1]);

        if (++buf == 3) buf = 0;
    }
#undef ISSUE

    // epilogue
#pragma unroll
    for (int mf = 0; mf < 4; ++mf) {
        int rr = m0 + warp_m + mf * 16 + (lane >> 2);
#pragma unroll
        for (int nf = 0; nf < 4; ++nf) {
            int cc = n0 + warp_n + nf * 8 + (lane & 3) * 2;
            float d0 = acc[mf][nf][0], d1 = acc[mf][nf][1];
            float d2 = acc[mf][nf][2], d3 = acc[mf][nf][3];
            if (extout) {
                if (rr < NNODES) {
                    if (cc < Nvalid)     extout[(size_t)rr * Nvalid + cc]     = d0 + bias[cc];
                    if (cc + 1 < Nvalid) extout[(size_t)rr * Nvalid + cc + 1] = d1 + bias[cc + 1];
                }
                if (rr + 8 < NNODES) {
                    if (cc < Nvalid)     extout[(size_t)(rr + 8) * Nvalid + cc]     = d2 + bias[cc];
                    if (cc + 1 < Nvalid) extout[(size_t)(rr + 8) * Nvalid + cc + 1] = d3 + bias[cc + 1];
                }
            } else {
                if (rr < NNODES)     *(float2*)&g_h[(size_t)rr * DH + cc]       = make_float2(d0, d1);
                if (rr + 8 < NNODES) *(float2*)&g_h[(size_t)(rr + 8) * DH + cc] = make_float2(d2, d3);
            }
        }
    }
}

// ---------------------------------------------------------------------------
// Aggregation: one block per node; writes split bf16 for next GEMM.
// ---------------------------------------------------------------------------
__global__ __launch_bounds__(128) void agg_kernel(
    const float* __restrict__ bias, int relu)
{
    int i = blockIdx.x;
    int tid = threadIdx.x;
    const float4* h4 = (const float4*)g_h;
    float di = g_dinv[i];
    int beg = g_rowptr[i];
    int end = g_rowptr[i + 1];

    float4 acc = make_float4(0.f, 0.f, 0.f, 0.f);
#pragma unroll 2
    for (int jj = beg; jj < end; ++jj) {
        int s = g_col[jj];
        float w = g_dinv[s] * di;
        float4 v = h4[(size_t)s * (DH / 4) + tid];
        acc.x += v.x * w;
        acc.y += v.y * w;
        acc.z += v.z * w;
        acc.w += v.w * w;
    }
    float sw = di * di;
    float4 self = h4[(size_t)i * (DH / 4) + tid];
    acc.x += self.x * sw;
    acc.y += self.y * sw;
    acc.z += self.z * sw;
    acc.w += self.w * sw;
    const float4* b4 = (const float4*)bias;
    float4 bb = b4[tid];
    acc.x += bb.x; acc.y += bb.y; acc.z += bb.z; acc.w += bb.w;
    if (relu) {
        acc.x = fmaxf(acc.x, 0.f);
        acc.y = fmaxf(acc.y, 0.f);
        acc.z = fmaxf(acc.z, 0.f);
        acc.w = fmaxf(acc.w, 0.f);
    }
    float v[4] = {acc.x, acc.y, acc.z, acc.w};
    __nv_bfloat16 hi[4], lo[4];
#pragma unroll
    for (int jj = 0; jj < 4; ++jj) split_bf16(v[jj], hi[jj], lo[jj]);
    ((uint2*)g_ahi)[(size_t)i * (DH / 4) + tid] = *(uint2*)hi;
    ((uint2*)g_alo)[(size_t)i * (DH / 4) + tid] = *(uint2*)lo;
}

// ---------------------------------------------------------------------------
extern "C" void kernel_launch(void* const* d_in, const int* in_sizes, int n_in,
                              void* d_out, int out_size) {
    const float* x  = (const float*)d_in[0];
    const int*   ei = (const int*)d_in[1];     // int32 (JAX x64 disabled)
    const float* W1 = (const float*)d_in[2];
    const float* b1 = (const float*)d_in[3];
    const float* W2 = (const float*)d_in[4];
    const float* b2 = (const float*)d_in[5];
    const float* Wc = (const float*)d_in[6];
    const float* bc = (const float*)d_in[7];
    float* out = (float*)d_out;

    int N = in_sizes[0] / DH;             // 10000
    int E = in_sizes[1] / 2;              // 160000
    int d_out_dim = in_sizes[6] / DH;     // 100

    // CSR build
    zero_cnt_kernel<<<(N + 255) / 256, 256>>>(N);
    count_kernel<<<(E + 255) / 256, 256>>>(ei, E, N);
    scan_kernel<<<1, 1024>>>(N);
    fill_kernel<<<(E + 255) / 256, 256>>>(ei, E, N);

    // operand prep
    conv_x_kernel<<<(N * DH / 8 + 255) / 256, 256>>>(x);
    dim3 tb(32, 32);
    prep_w_kernel<<<dim3(DH / 32, DH / 32), tb>>>(W1, DH, 0);
    prep_w_kernel<<<dim3(DH / 32, DH / 32), tb>>>(W2, DH, 1);
    prep_w_kernel<<<dim3(DH / 32, NPADC / 32), tb>>>(Wc, d_out_dim, 2);

    int mblocks = (N + BMt - 1) / BMt;    // 79

    // Layer 1
    mma_gemm_kernel<<<dim3(DH / BNt, mblocks), 256>>>(0, nullptr, nullptr, DH);
    agg_kernel<<<N, 128>>>(b1, 1);

    // Layer 2
    mma_gemm_kernel<<<dim3(DH / BNt, mblocks), 256>>>(1, nullptr, nullptr, DH);
    agg_kernel<<<N, 128>>>(b2, 0);

    // Classifier
    mma_gemm_kernel<<<dim3(1, mblocks), 256>>>(2, bc, out, d_out_dim);
}

// round 13
// speedup vs baseline: 1.6174x; 1.0391x over previous
#include <cuda_runtime.h>
#include <cuda_bf16.h>
#include <cstdint>

// ---------------------------------------------------------------------------
// CompressedGNN on GB300 (plain sm_103 target — no tcgen05 in harness PTX).
// GEMMs: mma.sync bf16 (HMMA), split-precision x3 fused. BM=64 tiles at
// 3 CTAs/SM to kill wave quantization (628 CTAs / 444 concurrent = 2 waves).
// Aggregation: CSR gather (atomic-free), fused bf16 hi/lo split output.
// ---------------------------------------------------------------------------

#define NNODES 10000
#define MAXE   160000
#define DH     512
#define NPADC  128

__device__ float g_h[NNODES * DH];              // fp32 GEMM output
__device__ uint4 g_ahi[NNODES * DH / 8];        // split A operand (8 bf16/uint4)
__device__ uint4 g_alo[NNODES * DH / 8];
__device__ uint4 g_w1hi[DH * DH / 8];           // transposed split weights [N][K]
__device__ uint4 g_w1lo[DH * DH / 8];
__device__ uint4 g_w2hi[DH * DH / 8];
__device__ uint4 g_w2lo[DH * DH / 8];
__device__ uint4 g_wchi[NPADC * DH / 8];
__device__ uint4 g_wclo[NPADC * DH / 8];
__device__ float g_dinv[NNODES];
__device__ int   g_cnt[NNODES];
__device__ int   g_rowptr[NNODES + 1];
__device__ int   g_cursor[NNODES];
__device__ int   g_col[MAXE];

// ---------------------------------------------------------------------------
__device__ __forceinline__ uint32_t smem_to_u32(const void* p) {
    uint32_t a;
    asm("{ .reg .u64 t; cvta.to.shared.u64 t, %1; cvt.u32.u64 %0, t; }"
        : "=r"(a) : "l"(p));
    return a;
}

__device__ __forceinline__ void ldmat_x4(uint32_t (&r)[4], uint32_t addr) {
    asm volatile("ldmatrix.sync.aligned.m8n8.x4.shared.b16 {%0,%1,%2,%3}, [%4];"
                 : "=r"(r[0]), "=r"(r[1]), "=r"(r[2]), "=r"(r[3]) : "r"(addr));
}

__device__ __forceinline__ void mma_bf16(float (&d)[4], const uint32_t (&a)[4],
                                         uint32_t b0, uint32_t b1) {
    asm volatile("mma.sync.aligned.m16n8k16.row.col.f32.bf16.bf16.f32 "
                 "{%0,%1,%2,%3}, {%4,%5,%6,%7}, {%8,%9}, {%0,%1,%2,%3};"
                 : "+f"(d[0]), "+f"(d[1]), "+f"(d[2]), "+f"(d[3])
                 : "r"(a[0]), "r"(a[1]), "r"(a[2]), "r"(a[3]), "r"(b0), "r"(b1));
}

__device__ __forceinline__ void cp16(uint32_t dst, const void* src, bool valid) {
    int sz = valid ? 16 : 0;
    asm volatile("cp.async.cg.shared.global [%0], [%1], 16, %2;"
                 :: "r"(dst), "l"(src), "r"(sz) : "memory");
}
#define CP_COMMIT() asm volatile("cp.async.commit_group;" ::: "memory")
#define CP_WAIT0()  asm volatile("cp.async.wait_group 0;" ::: "memory")
#define CP_WAIT1()  asm volatile("cp.async.wait_group 1;" ::: "memory")

// ---------------------------------------------------------------------------
// CSR build
// ---------------------------------------------------------------------------
__global__ void zero_cnt_kernel(int n) {
    int i = blockIdx.x * blockDim.x + threadIdx.x;
    if (i < n) g_cnt[i] = 0;
}

__global__ void count_kernel(const int* __restrict__ ei, int E, int n) {
    int e = blockIdx.x * blockDim.x + threadIdx.x;
    if (e < E) {
        int d = ei[E + e];
        if (d >= 0 && d < n) atomicAdd(&g_cnt[d], 1);
    }
}

__global__ void scan_kernel(int n) {
    __shared__ int part[1024];
    int tid = threadIdx.x;
    int CH = (n + 1023) / 1024;
    int base = tid * CH;
    int s = 0;
    for (int i = 0; i < CH; ++i) {
        int idx = base + i;
        if (idx < n) s += g_cnt[idx];
    }
    part[tid] = s;
    __syncthreads();
    for (int off = 1; off < 1024; off <<= 1) {
        int add = (tid >= off) ? part[tid - off] : 0;
        __syncthreads();
        part[tid] += add;
        __syncthreads();
    }
    int run = part[tid] - s;
    for (int i = 0; i < CH; ++i) {
        int idx = base + i;
        if (idx < n) {
            g_rowptr[idx] = run;
            g_cursor[idx] = run;
            int c = g_cnt[idx];
            g_dinv[idx] = rsqrtf(1.0f + (float)c);
            run += c;
        }
    }
    if (tid == 0) g_rowptr[n] = part[1023];
}

__global__ void fill_kernel(const int* __restrict__ ei, int E, int n) {
    int e = blockIdx.x * blockDim.x + threadIdx.x;
    if (e < E) {
        int s = ei[e];
        int d = ei[E + e];
        if (d >= 0 && d < n && s >= 0 && s < n) {
            int pos = atomicAdd(&g_cursor[d], 1);
            g_col[pos] = s;
        }
    }
}

// ---------------------------------------------------------------------------
// bf16 split prep
// ---------------------------------------------------------------------------
__device__ __forceinline__ void split_bf16(float v, __nv_bfloat16& hi, __nv_bfloat16& lo) {
    hi = __float2bfloat16(v);
    lo = __float2bfloat16(v - __bfloat162float(hi));
}

__global__ void conv_x_kernel(const float* __restrict__ x) {
    int idx = blockIdx.x * blockDim.x + threadIdx.x;
    int total = NNODES * DH / 8;
    if (idx >= total) return;
    const float4* p = (const float4*)x;
    float4 a = p[idx * 2], b = p[idx * 2 + 1];
    float v[8] = {a.x, a.y, a.z, a.w, b.x, b.y, b.z, b.w};
    __nv_bfloat16 hi[8], lo[8];
#pragma unroll
    for (int j = 0; j < 8; ++j) split_bf16(v[j], hi[j], lo[j]);
    g_ahi[idx] = *(uint4*)hi;
    g_alo[idx] = *(uint4*)lo;
}

// Transpose + split all three weights in one launch; z selects the weight.
__global__ void prep_w_kernel(const float* __restrict__ W1,
                              const float* __restrict__ W2,
                              const float* __restrict__ Wc, int NcOut) {
    int which = blockIdx.z;
    if (which == 2 && blockIdx.y >= NPADC / 32) return;
    const float* W = (which == 0) ? W1 : (which == 1) ? W2 : Wc;
    int N = (which == 2) ? NcOut : DH;
    __shared__ float t[32][33];
    int k0 = blockIdx.x * 32, n0 = blockIdx.y * 32;
    int tx = threadIdx.x, ty = threadIdx.y;
    int k = k0 + ty, n = n0 + tx;
    float v = 0.0f;
    if (n < N) v = W[(size_t)k * N + n];
    t[ty][tx] = v;
    __syncthreads();
    int on = n0 + ty, ok = k0 + tx;
    float w = t[tx][ty];
    __nv_bfloat16 hi, lo;
    split_bf16(w, hi, lo);
    __nv_bfloat16 *dh, *dl;
    if (which == 0)      { dh = (__nv_bfloat16*)g_w1hi; dl = (__nv_bfloat16*)g_w1lo; }
    else if (which == 1) { dh = (__nv_bfloat16*)g_w2hi; dl = (__nv_bfloat16*)g_w2lo; }
    else                 { dh = (__nv_bfloat16*)g_wchi; dl = (__nv_bfloat16*)g_wclo; }
    dh[(size_t)on * DH + ok] = hi;
    dl[(size_t)on * DH + ok] = lo;
}

// ---------------------------------------------------------------------------
// HMMA GEMM, fused split passes. 64x128 CTA tile, BK=16, 8 warps (2x4),
// warp tile 32x32, 3 CTAs/SM. Smem: 32B permuted rows, 3-stage pipeline.
// Stage layout: Ahi(2K) | Alo(2K) | Bhi(4K) | Blo(4K) = 12KB.
// ---------------------------------------------------------------------------
#define BMt 64
#define BNt 128
#define BKt 16
#define TILEA 2048
#define TILEB 4096
#define STAGEB 12288
#define OFF_ALO 2048
#define OFF_BHI 4096
#define OFF_BLO 8192
#define NCH (DH / BKt)                // 32 k-chunks

__global__ __launch_bounds__(256, 3)
void mma_gemm_kernel(int which, const float* __restrict__ bias,
                     float* __restrict__ extout, int Nvalid)
{
    __shared__ __align__(128) char sMem[3 * STAGEB];   // 36864 B

    int tid = threadIdx.x, lane = tid & 31, wid = tid >> 5;
    int m0 = blockIdx.y * BMt, n0 = blockIdx.x * BNt;
    int warp_m = (wid >> 2) * 32, warp_n = (wid & 3) * 32;

    const uint4 *Wh, *Wl;
    if (which == 0)      { Wh = g_w1hi; Wl = g_w1lo; }
    else if (which == 1) { Wh = g_w2hi; Wl = g_w2lo; }
    else                 { Wh = g_wchi; Wl = g_wclo; }

    uint32_t base = smem_to_u32(sMem);

    // A loader: t<128 -> Ahi, t>=128 -> Alo. row = (t&127)>>1, j = t&1.
    int ta = tid & 127;
    int rA = ta >> 1, jA = tid & 1;
    const uint4* aSrcBase = (tid < 128) ? g_ahi : g_alo;
    uint32_t aDst = (uint32_t)((tid < 128 ? 0 : OFF_ALO) +
                               rA * 32 + ((jA ^ ((rA >> 2) & 1)) * 16));
    bool avalid = (m0 + rA) < NNODES;
    size_t aRow = (size_t)(m0 + rA) * (DH / 8) + jA;
    // B loader: every thread does one Bhi + one Blo 16B chunk.
    int rB = tid >> 1, jB = tid & 1;
    uint32_t bDst = (uint32_t)(rB * 32 + ((jB ^ ((rB >> 2) & 1)) * 16));
    size_t bRow = (size_t)(n0 + rB) * (DH / 8) + jB;

    float acc[2][4][4];
#pragma unroll
    for (int a = 0; a < 2; ++a)
#pragma unroll
        for (int b = 0; b < 4; ++b)
#pragma unroll
            for (int c = 0; c < 4; ++c) acc[a][b][c] = 0.0f;

#define ISSUE(it, buf) do {                                                  \
        size_t _ko = (size_t)(it) * 2;                                       \
        uint32_t _s = base + (buf) * STAGEB;                                 \
        cp16(_s + aDst,           aSrcBase + aRow + _ko, avalid);            \
        cp16(_s + OFF_BHI + bDst, Wh + bRow + _ko, true);                    \
        cp16(_s + OFF_BLO + bDst, Wl + bRow + _ko, true);                    \
    } while (0)

    ISSUE(0, 0);
    CP_COMMIT();
    ISSUE(1, 1);
    CP_COMMIT();

    // fragment smem offsets (constant across iterations; permuted chunks)
    uint32_t aFragOff[2], bFragOff[2];
#pragma unroll
    for (int mf = 0; mf < 2; ++mf) {
        int row = warp_m + mf * 16 + (lane & 15);
        int cs = (lane >> 4) ^ ((row >> 2) & 1);
        aFragOff[mf] = (uint32_t)(row * 32 + cs * 16);
    }
#pragma unroll
    for (int nb = 0; nb < 2; ++nb) {
        int nrow = warp_n + nb * 16 + ((lane >> 4) << 3) + (lane & 7);
        int cs = ((lane >> 3) & 1) ^ ((nrow >> 2) & 1);
        bFragOff[nb] = (uint32_t)(nrow * 32 + cs * 16);
    }

    int buf = 0;
    for (int it = 0; it < NCH; ++it) {
        if (it + 1 < NCH) CP_WAIT1(); else CP_WAIT0();
        __syncthreads();

        if (it + 2 < NCH) {
            int buf2 = buf + 2; if (buf2 >= 3) buf2 -= 3;
            ISSUE(it + 2, buf2);
            CP_COMMIT();
        }

        uint32_t sb = base + buf * STAGEB;
        uint32_t ahi[2][4], bhi[2][4], blo[2][4];
#pragma unroll
        for (int mf = 0; mf < 2; ++mf) ldmat_x4(ahi[mf], sb + aFragOff[mf]);
#pragma unroll
        for (int nb = 0; nb < 2; ++nb) {
            ldmat_x4(bhi[nb], sb + OFF_BHI + bFragOff[nb]);
            ldmat_x4(blo[nb], sb + OFF_BLO + bFragOff[nb]);
        }
        // HH
#pragma unroll
        for (int mf = 0; mf < 2; ++mf)
#pragma unroll
            for (int nf = 0; nf < 4; ++nf)
                mma_bf16(acc[mf][nf], ahi[mf],
                         bhi[nf >> 1][(nf & 1) * 2], bhi[nf >> 1][(nf & 1) * 2 + 1]);
        // HL
#pragma unroll
        for (int mf = 0; mf < 2; ++mf)
#pragma unroll
            for (int nf = 0; nf < 4; ++nf)
                mma_bf16(acc[mf][nf], ahi[mf],
                         blo[nf >> 1][(nf & 1) * 2], blo[nf >> 1][(nf & 1) * 2 + 1]);
        // LH
        uint32_t alo[2][4];
#pragma unroll
        for (int mf = 0; mf < 2; ++mf) ldmat_x4(alo[mf], sb + OFF_ALO + aFragOff[mf]);
#pragma unroll
        for (int mf = 0; mf < 2; ++mf)
#pragma unroll
            for (int nf = 0; nf < 4; ++nf)
                mma_bf16(acc[mf][nf], alo[mf],
                         bhi[nf >> 1][(nf & 1) * 2], bhi[nf >> 1][(nf & 1) * 2 + 1]);

        if (++buf == 3) buf = 0;
    }
#undef ISSUE

    // epilogue
#pragma unroll
    for (int mf = 0; mf < 2; ++mf) {
        int rr = m0 + warp_m + mf * 16 + (lane >> 2);
#pragma unroll
        for (int nf = 0; nf < 4; ++nf) {
            int cc = n0 + warp_n + nf * 8 + (lane & 3) * 2;
            float d0 = acc[mf][nf][0], d1 = acc[mf][nf][1];
            float d2 = acc[mf][nf][2], d3 = acc[mf][nf][3];
            if (extout) {
                if (rr < NNODES) {
                    if (cc < Nvalid)     extout[(size_t)rr * Nvalid + cc]     = d0 + bias[cc];
                    if (cc + 1 < Nvalid) extout[(size_t)rr * Nvalid + cc + 1] = d1 + bias[cc + 1];
                }
                if (rr + 8 < NNODES) {
                    if (cc < Nvalid)     extout[(size_t)(rr + 8) * Nvalid + cc]     = d2 + bias[cc];
                    if (cc + 1 < Nvalid) extout[(size_t)(rr + 8) * Nvalid + cc + 1] = d3 + bias[cc + 1];
                }
            } else {
                if (rr < NNODES)     *(float2*)&g_h[(size_t)rr * DH + cc]       = make_float2(d0, d1);
                if (rr + 8 < NNODES) *(float2*)&g_h[(size_t)(rr + 8) * DH + cc] = make_float2(d2, d3);
            }
        }
    }
}

// ---------------------------------------------------------------------------
// Aggregation: one block per node; writes split bf16 for next GEMM.
// ---------------------------------------------------------------------------
__global__ __launch_bounds__(128) void agg_kernel(
    const float* __restrict__ bias, int relu)
{
    int i = blockIdx.x;
    int tid = threadIdx.x;
    const float4* h4 = (const float4*)g_h;
    float di = g_dinv[i];
    int beg = g_rowptr[i];
    int end = g_rowptr[i + 1];

    float4 acc = make_float4(0.f, 0.f, 0.f, 0.f);
#pragma unroll 2
    for (int jj = beg; jj < end; ++jj) {
        int s = g_col[jj];
        float w = g_dinv[s] * di;
        float4 v = h4[(size_t)s * (DH / 4) + tid];
        acc.x += v.x * w;
        acc.y += v.y * w;
        acc.z += v.z * w;
        acc.w += v.w * w;
    }
    float sw = di * di;
    float4 self = h4[(size_t)i * (DH / 4) + tid];
    acc.x += self.x * sw;
    acc.y += self.y * sw;
    acc.z += self.z * sw;
    acc.w += self.w * sw;
    const float4* b4 = (const float4*)bias;
    float4 bb = b4[tid];
    acc.x += bb.x; acc.y += bb.y; acc.z += bb.z; acc.w += bb.w;
    if (relu) {
        acc.x = fmaxf(acc.x, 0.f);
        acc.y = fmaxf(acc.y, 0.f);
        acc.z = fmaxf(acc.z, 0.f);
        acc.w = fmaxf(acc.w, 0.f);
    }
    float v[4] = {acc.x, acc.y, acc.z, acc.w};
    __nv_bfloat16 hi[4], lo[4];
#pragma unroll
    for (int jj = 0; jj < 4; ++jj) split_bf16(v[jj], hi[jj], lo[jj]);
    ((uint2*)g_ahi)[(size_t)i * (DH / 4) + tid] = *(uint2*)hi;
    ((uint2*)g_alo)[(size_t)i * (DH / 4) + tid] = *(uint2*)lo;
}

// ---------------------------------------------------------------------------
extern "C" void kernel_launch(void* const* d_in, const int* in_sizes, int n_in,
                              void* d_out, int out_size) {
    const float* x  = (const float*)d_in[0];
    const int*   ei = (const int*)d_in[1];     // int32 (JAX x64 disabled)
    const float* W1 = (const float*)d_in[2];
    const float* b1 = (const float*)d_in[3];
    const float* W2 = (const float*)d_in[4];
    const float* b2 = (const float*)d_in[5];
    const float* Wc = (const float*)d_in[6];
    const float* bc = (const float*)d_in[7];
    float* out = (float*)d_out;

    int N = in_sizes[0] / DH;             // 10000
    int E = in_sizes[1] / 2;              // 160000
    int d_out_dim = in_sizes[6] / DH;     // 100

    // CSR build
    zero_cnt_kernel<<<(N + 255) / 256, 256>>>(N);
    count_kernel<<<(E + 255) / 256, 256>>>(ei, E, N);
    scan_kernel<<<1, 1024>>>(N);
    fill_kernel<<<(E + 255) / 256, 256>>>(ei, E, N);

    // operand prep
    conv_x_kernel<<<(N * DH / 8 + 255) / 256, 256>>>(x);
    prep_w_kernel<<<dim3(DH / 32, DH / 32, 3), dim3(32, 32)>>>(W1, W2, Wc, d_out_dim);

    int mblocks = (N + BMt - 1) / BMt;    // 157

    // Layer 1
    mma_gemm_kernel<<<dim3(DH / BNt, mblocks), 256>>>(0, nullptr, nullptr, DH);
    agg_kernel<<<N, 128>>>(b1, 1);

    // Layer 2
    mma_gemm_kernel<<<dim3(DH / BNt, mblocks), 256>>>(1, nullptr, nullptr, DH);
    agg_kernel<<<N, 128>>>(b2, 0);

    // Classifier
    mma_gemm_kernel<<<dim3(1, mblocks), 256>>>(2, bc, out, d_out_dim);
}

// round 14
// speedup vs baseline: 1.6601x; 1.0264x over previous
#include <cuda_runtime.h>
#include <cuda_bf16.h>
#include <cstdint>

// ---------------------------------------------------------------------------
// CompressedGNN on GB300 (plain sm_103 target — no tcgen05 in harness PTX).
// GEMMs: mma.sync bf16 (HMMA), split-precision x3 fused, BM=64 @ 3 CTAs/SM.
// Prep (zero + x-split + weight transpose/split) merged into one launch.
// Aggregation: CSR gather (atomic-free), fused bf16 hi/lo split output.
// ---------------------------------------------------------------------------

#define NNODES 10000
#define MAXE   160000
#define DH     512
#define NPADC  128

__device__ float g_h[NNODES * DH];              // fp32 GEMM output
__device__ uint4 g_ahi[NNODES * DH / 8];        // split A operand (8 bf16/uint4)
__device__ uint4 g_alo[NNODES * DH / 8];
__device__ uint4 g_w1hi[DH * DH / 8];           // transposed split weights [N][K]
__device__ uint4 g_w1lo[DH * DH / 8];
__device__ uint4 g_w2hi[DH * DH / 8];
__device__ uint4 g_w2lo[DH * DH / 8];
__device__ uint4 g_wchi[NPADC * DH / 8];
__device__ uint4 g_wclo[NPADC * DH / 8];
__device__ float g_dinv[NNODES];
__device__ int   g_cnt[NNODES];
__device__ int   g_rowptr[NNODES + 1];
__device__ int   g_cursor[NNODES];
__device__ int   g_col[MAXE];

// ---------------------------------------------------------------------------
__device__ __forceinline__ uint32_t smem_to_u32(const void* p) {
    uint32_t a;
    asm("{ .reg .u64 t; cvta.to.shared.u64 t, %1; cvt.u32.u64 %0, t; }"
        : "=r"(a) : "l"(p));
    return a;
}

__device__ __forceinline__ void ldmat_x4(uint32_t (&r)[4], uint32_t addr) {
    asm volatile("ldmatrix.sync.aligned.m8n8.x4.shared.b16 {%0,%1,%2,%3}, [%4];"
                 : "=r"(r[0]), "=r"(r[1]), "=r"(r[2]), "=r"(r[3]) : "r"(addr));
}

__device__ __forceinline__ void mma_bf16(float (&d)[4], const uint32_t (&a)[4],
                                         uint32_t b0, uint32_t b1) {
    asm volatile("mma.sync.aligned.m16n8k16.row.col.f32.bf16.bf16.f32 "
                 "{%0,%1,%2,%3}, {%4,%5,%6,%7}, {%8,%9}, {%0,%1,%2,%3};"
                 : "+f"(d[0]), "+f"(d[1]), "+f"(d[2]), "+f"(d[3])
                 : "r"(a[0]), "r"(a[1]), "r"(a[2]), "r"(a[3]), "r"(b0), "r"(b1));
}

__device__ __forceinline__ void cp16(uint32_t dst, const void* src, bool valid) {
    int sz = valid ? 16 : 0;
    asm volatile("cp.async.cg.shared.global [%0], [%1], 16, %2;"
                 :: "r"(dst), "l"(src), "r"(sz) : "memory");
}
#define CP_COMMIT() asm volatile("cp.async.commit_group;" ::: "memory")
#define CP_WAIT0()  asm volatile("cp.async.wait_group 0;" ::: "memory")
#define CP_WAIT1()  asm volatile("cp.async.wait_group 1;" ::: "memory")

// ---------------------------------------------------------------------------
// bf16 split helper
// ---------------------------------------------------------------------------
__device__ __forceinline__ void split_bf16(float v, __nv_bfloat16& hi, __nv_bfloat16& lo) {
    hi = __float2bfloat16(v);
    lo = __float2bfloat16(v - __bfloat162float(hi));
}

// ---------------------------------------------------------------------------
// Merged prep: [0,2500) conv_x | [2500,2540) zero cnt | [2540,3116) weight prep
// ---------------------------------------------------------------------------
#define CONV_BLOCKS 2500
#define ZERO_BLOCKS 40
#define W1_TILES 256           // 16 k-tiles x 16 n-tiles
#define W2_TILES 256
#define WC_TILES 64            // 16 k-tiles x 4 n-tiles
#define PREP_BLOCKS (CONV_BLOCKS + ZERO_BLOCKS + W1_TILES + W2_TILES + WC_TILES)

__global__ __launch_bounds__(256) void prep_all_kernel(
    const float* __restrict__ x,
    const float* __restrict__ W1, const float* __restrict__ W2,
    const float* __restrict__ Wc, int NcOut)
{
    int b = blockIdx.x, tid = threadIdx.x;

    if (b < CONV_BLOCKS) {
        // conv_x: split x into g_ahi/g_alo, 8 floats per thread
        int idx = b * 256 + tid;
        const float4* p = (const float4*)x;
        float4 a = p[idx * 2], b4 = p[idx * 2 + 1];
        float v[8] = {a.x, a.y, a.z, a.w, b4.x, b4.y, b4.z, b4.w};
        __nv_bfloat16 hi[8], lo[8];
#pragma unroll
        for (int j = 0; j < 8; ++j) split_bf16(v[j], hi[j], lo[j]);
        g_ahi[idx] = *(uint4*)hi;
        g_alo[idx] = *(uint4*)lo;
        return;
    }
    b -= CONV_BLOCKS;
    if (b < ZERO_BLOCKS) {
        int i = b * 256 + tid;
        if (i < NNODES) g_cnt[i] = 0;
        return;
    }
    b -= ZERO_BLOCKS;

    // weight transpose + split, 32x32 tile per block, 256 threads (4 rows each)
    int which, tileIdx, ntn;
    if (b < W1_TILES)                { which = 0; tileIdx = b;             ntn = 16; }
    else if (b < W1_TILES + W2_TILES){ which = 1; tileIdx = b - W1_TILES;  ntn = 16; }
    else                             { which = 2; tileIdx = b - W1_TILES - W2_TILES; ntn = 4; }
    const float* W = (which == 0) ? W1 : (which == 1) ? W2 : Wc;
    int N = (which == 2) ? NcOut : DH;
    int k0 = (tileIdx / ntn) * 32, n0 = (tileIdx % ntn) * 32;

    __shared__ float t[32][33];
    int tx = tid & 31, tyb = tid >> 5;
#pragma unroll
    for (int r = 0; r < 4; ++r) {
        int ty = tyb + r * 8;
        int n = n0 + tx;
        float v = 0.0f;
        if (n < N) v = W[(size_t)(k0 + ty) * N + n];
        t[ty][tx] = v;
    }
    __syncthreads();
    __nv_bfloat16 *dh, *dl;
    if (which == 0)      { dh = (__nv_bfloat16*)g_w1hi; dl = (__nv_bfloat16*)g_w1lo; }
    else if (which == 1) { dh = (__nv_bfloat16*)g_w2hi; dl = (__nv_bfloat16*)g_w2lo; }
    else                 { dh = (__nv_bfloat16*)g_wchi; dl = (__nv_bfloat16*)g_wclo; }
#pragma unroll
    for (int r = 0; r < 4; ++r) {
        int ty = tyb + r * 8;
        float w = t[tx][ty];
        __nv_bfloat16 hi, lo;
        split_bf16(w, hi, lo);
        size_t o = (size_t)(n0 + ty) * DH + (k0 + tx);
        dh[o] = hi;
        dl[o] = lo;
    }
}

// ---------------------------------------------------------------------------
// CSR build
// ---------------------------------------------------------------------------
__global__ void count_kernel(const int* __restrict__ ei, int E, int n) {
    int e = blockIdx.x * blockDim.x + threadIdx.x;
    if (e < E) {
        int d = ei[E + e];
        if (d >= 0 && d < n) atomicAdd(&g_cnt[d], 1);
    }
}

// Shuffle-based single-block scan (2 barriers).
__global__ void scan_kernel(int n) {
    __shared__ int wsum[32], woff[32];
    int tid = threadIdx.x, lane = tid & 31, wid = tid >> 5;
    int CH = (n + 1023) >> 10;           // 10 for n=10000
    int base = tid * CH;
    int cl[16];
    int s = 0;
#pragma unroll 10
    for (int i = 0; i < CH; ++i) {
        int idx = base + i;
        int c = (idx < n) ? g_cnt[idx] : 0;
        cl[i] = c;
        s += c;
    }
    int mysum = s;
#pragma unroll
    for (int off = 1; off < 32; off <<= 1) {
        int v = __shfl_up_sync(0xffffffffu, s, off);
        if (lane >= off) s += v;
    }
    if (lane == 31) wsum[wid] = s;
    __syncthreads();
    if (wid == 0) {
        int t0 = wsum[lane];
        int ts = t0;
#pragma unroll
        for (int off = 1; off < 32; off <<= 1) {
            int v = __shfl_up_sync(0xffffffffu, ts, off);
            if (lane >= off) ts += v;
        }
        woff[lane] = ts - t0;
        if (lane == 31) g_rowptr[n] = ts;
    }
    __syncthreads();
    int run = woff[wid] + (s - mysum);
#pragma unroll 10
    for (int i = 0; i < CH; ++i) {
        int idx = base + i;
        if (idx < n) {
            g_rowptr[idx] = run;
            g_cursor[idx] = run;
            int c = cl[i];
            g_dinv[idx] = rsqrtf(1.0f + (float)c);
            run += c;
        }
    }
}

__global__ void fill_kernel(const int* __restrict__ ei, int E, int n) {
    int e = blockIdx.x * blockDim.x + threadIdx.x;
    if (e < E) {
        int s = ei[e];
        int d = ei[E + e];
        if (d >= 0 && d < n && s >= 0 && s < n) {
            int pos = atomicAdd(&g_cursor[d], 1);
            g_col[pos] = s;
        }
    }
}

// ---------------------------------------------------------------------------
// HMMA GEMM, fused split passes. 64x128 CTA tile, BK=16, 8 warps (2x4),
// warp tile 32x32, 3 CTAs/SM. Smem: 32B permuted rows, 3-stage pipeline.
// Stage layout: Ahi(2K) | Alo(2K) | Bhi(4K) | Blo(4K) = 12KB.
// ---------------------------------------------------------------------------
#define BMt 64
#define BNt 128
#define BKt 16
#define STAGEB 12288
#define OFF_ALO 2048
#define OFF_BHI 4096
#define OFF_BLO 8192
#define NCH (DH / BKt)                // 32 k-chunks

__global__ __launch_bounds__(256, 3)
void mma_gemm_kernel(int which, const float* __restrict__ bias,
                     float* __restrict__ extout, int Nvalid)
{
    __shared__ __align__(128) char sMem[3 * STAGEB];   // 36864 B

    int tid = threadIdx.x, lane = tid & 31, wid = tid >> 5;
    int m0 = blockIdx.y * BMt, n0 = blockIdx.x * BNt;
    int warp_m = (wid >> 2) * 32, warp_n = (wid & 3) * 32;

    const uint4 *Wh, *Wl;
    if (which == 0)      { Wh = g_w1hi; Wl = g_w1lo; }
    else if (which == 1) { Wh = g_w2hi; Wl = g_w2lo; }
    else                 { Wh = g_wchi; Wl = g_wclo; }

    uint32_t base = smem_to_u32(sMem);

    // A loader: t<128 -> Ahi, t>=128 -> Alo. row = (t&127)>>1, j = t&1.
    int ta = tid & 127;
    int rA = ta >> 1, jA = tid & 1;
    const uint4* aSrcBase = (tid < 128) ? g_ahi : g_alo;
    uint32_t aDst = (uint32_t)((tid < 128 ? 0 : OFF_ALO) +
                               rA * 32 + ((jA ^ ((rA >> 2) & 1)) * 16));
    bool avalid = (m0 + rA) < NNODES;
    size_t aRow = (size_t)(m0 + rA) * (DH / 8) + jA;
    // B loader: every thread does one Bhi + one Blo 16B chunk.
    int rB = tid >> 1, jB = tid & 1;
    uint32_t bDst = (uint32_t)(rB * 32 + ((jB ^ ((rB >> 2) & 1)) * 16));
    size_t bRow = (size_t)(n0 + rB) * (DH / 8) + jB;

    float acc[2][4][4];
#pragma unroll
    for (int a = 0; a < 2; ++a)
#pragma unroll
        for (int b = 0; b < 4; ++b)
#pragma unroll
            for (int c = 0; c < 4; ++c) acc[a][b][c] = 0.0f;

#define ISSUE(it, buf) do {                                                  \
        size_t _ko = (size_t)(it) * 2;                                       \
        uint32_t _s = base + (buf) * STAGEB;                                 \
        cp16(_s + aDst,           aSrcBase + aRow + _ko, avalid);            \
        cp16(_s + OFF_BHI + bDst, Wh + bRow + _ko, true);                    \
        cp16(_s + OFF_BLO + bDst, Wl + bRow + _ko, true);                    \
    } while (0)

    ISSUE(0, 0);
    CP_COMMIT();
    ISSUE(1, 1);
    CP_COMMIT();

    // fragment smem offsets (constant across iterations; permuted chunks)
    uint32_t aFragOff[2], bFragOff[2];
#pragma unroll
    for (int mf = 0; mf < 2; ++mf) {
        int row = warp_m + mf * 16 + (lane & 15);
        int cs = (lane >> 4) ^ ((row >> 2) & 1);
        aFragOff[mf] = (uint32_t)(row * 32 + cs * 16);
    }
#pragma unroll
    for (int nb = 0; nb < 2; ++nb) {
        int nrow = warp_n + nb * 16 + ((lane >> 4) << 3) + (lane & 7);
        int cs = ((lane >> 3) & 1) ^ ((nrow >> 2) & 1);
        bFragOff[nb] = (uint32_t)(nrow * 32 + cs * 16);
    }

    int buf = 0;
    for (int it = 0; it < NCH; ++it) {
        if (it + 1 < NCH) CP_WAIT1(); else CP_WAIT0();
        __syncthreads();

        if (it + 2 < NCH) {
            int buf2 = buf + 2; if (buf2 >= 3) buf2 -= 3;
            ISSUE(it + 2, buf2);
            CP_COMMIT();
        }

        uint32_t sb = base + buf * STAGEB;
        uint32_t ahi[2][4], bhi[2][4], blo[2][4];
#pragma unroll
        for (int mf = 0; mf < 2; ++mf) ldmat_x4(ahi[mf], sb + aFragOff[mf]);
#pragma unroll
        for (int nb = 0; nb < 2; ++nb) {
            ldmat_x4(bhi[nb], sb + OFF_BHI + bFragOff[nb]);
            ldmat_x4(blo[nb], sb + OFF_BLO + bFragOff[nb]);
        }
        // HH
#pragma unroll
        for (int mf = 0; mf < 2; ++mf)
#pragma unroll
            for (int nf = 0; nf < 4; ++nf)
                mma_bf16(acc[mf][nf], ahi[mf],
                         bhi[nf >> 1][(nf & 1) * 2], bhi[nf >> 1][(nf & 1) * 2 + 1]);
        // HL
#pragma unroll
        for (int mf = 0; mf < 2; ++mf)
#pragma unroll
            for (int nf = 0; nf < 4; ++nf)
                mma_bf16(acc[mf][nf], ahi[mf],
                         blo[nf >> 1][(nf & 1) * 2], blo[nf >> 1][(nf & 1) * 2 + 1]);
        // LH
        uint32_t alo[2][4];
#pragma unroll
        for (int mf = 0; mf < 2; ++mf) ldmat_x4(alo[mf], sb + OFF_ALO + aFragOff[mf]);
#pragma unroll
        for (int mf = 0; mf < 2; ++mf)
#pragma unroll
            for (int nf = 0; nf < 4; ++nf)
                mma_bf16(acc[mf][nf], alo[mf],
                         bhi[nf >> 1][(nf & 1) * 2], bhi[nf >> 1][(nf & 1) * 2 + 1]);

        if (++buf == 3) buf = 0;
    }
#undef ISSUE

    // epilogue
#pragma unroll
    for (int mf = 0; mf < 2; ++mf) {
        int rr = m0 + warp_m + mf * 16 + (lane >> 2);
#pragma unroll
        for (int nf = 0; nf < 4; ++nf) {
            int cc = n0 + warp_n + nf * 8 + (lane & 3) * 2;
            float d0 = acc[mf][nf][0], d1 = acc[mf][nf][1];
            float d2 = acc[mf][nf][2], d3 = acc[mf][nf][3];
            if (extout) {
                if (rr < NNODES) {
                    if (cc < Nvalid)     extout[(size_t)rr * Nvalid + cc]     = d0 + bias[cc];
                    if (cc + 1 < Nvalid) extout[(size_t)rr * Nvalid + cc + 1] = d1 + bias[cc + 1];
                }
                if (rr + 8 < NNODES) {
                    if (cc < Nvalid)     extout[(size_t)(rr + 8) * Nvalid + cc]     = d2 + bias[cc];
                    if (cc + 1 < Nvalid) extout[(size_t)(rr + 8) * Nvalid + cc + 1] = d3 + bias[cc + 1];
                }
            } else {
                if (rr < NNODES)     *(float2*)&g_h[(size_t)rr * DH + cc]       = make_float2(d0, d1);
                if (rr + 8 < NNODES) *(float2*)&g_h[(size_t)(rr + 8) * DH + cc] = make_float2(d2, d3);
            }
        }
    }
}

// ---------------------------------------------------------------------------
// Aggregation: one block per node; writes split bf16 for next GEMM.
// ---------------------------------------------------------------------------
__global__ __launch_bounds__(128) void agg_kernel(
    const float* __restrict__ bias, int relu)
{
    int i = blockIdx.x;
    int tid = threadIdx.x;
    const float4* h4 = (const float4*)g_h;
    float di = g_dinv[i];
    int beg = g_rowptr[i];
    int end = g_rowptr[i + 1];

    float4 acc = make_float4(0.f, 0.f, 0.f, 0.f);
#pragma unroll 2
    for (int jj = beg; jj < end; ++jj) {
        int s = g_col[jj];
        float w = g_dinv[s] * di;
        float4 v = h4[(size_t)s * (DH / 4) + tid];
        acc.x += v.x * w;
        acc.y += v.y * w;
        acc.z += v.z * w;
        acc.w += v.w * w;
    }
    float sw = di * di;
    float4 self = h4[(size_t)i * (DH / 4) + tid];
    acc.x += self.x * sw;
    acc.y += self.y * sw;
    acc.z += self.z * sw;
    acc.w += self.w * sw;
    const float4* b4 = (const float4*)bias;
    float4 bb = b4[tid];
    acc.x += bb.x; acc.y += bb.y; acc.z += bb.z; acc.w += bb.w;
    if (relu) {
        acc.x = fmaxf(acc.x, 0.f);
        acc.y = fmaxf(acc.y, 0.f);
        acc.z = fmaxf(acc.z, 0.f);
        acc.w = fmaxf(acc.w, 0.f);
    }
    float v[4] = {acc.x, acc.y, acc.z, acc.w};
    __nv_bfloat16 hi[4], lo[4];
#pragma unroll
    for (int jj = 0; jj < 4; ++jj) split_bf16(v[jj], hi[jj], lo[jj]);
    ((uint2*)g_ahi)[(size_t)i * (DH / 4) + tid] = *(uint2*)hi;
    ((uint2*)g_alo)[(size_t)i * (DH / 4) + tid] = *(uint2*)lo;
}

// ---------------------------------------------------------------------------
extern "C" void kernel_launch(void* const* d_in, const int* in_sizes, int n_in,
                              void* d_out, int out_size) {
    const float* x  = (const float*)d_in[0];
    const int*   ei = (const int*)d_in[1];     // int32 (JAX x64 disabled)
    const float* W1 = (const float*)d_in[2];
    const float* b1 = (const float*)d_in[3];
    const float* W2 = (const float*)d_in[4];
    const float* b2 = (const float*)d_in[5];
    const float* Wc = (const float*)d_in[6];
    const float* bc = (const float*)d_in[7];
    float* out = (float*)d_out;

    int N = in_sizes[0] / DH;             // 10000
    int E = in_sizes[1] / 2;              // 160000
    int d_out_dim = in_sizes[6] / DH;     // 100

    // Merged prep: conv_x + zero_cnt + weight transpose/split
    prep_all_kernel<<<PREP_BLOCKS, 256>>>(x, W1, W2, Wc, d_out_dim);

    // CSR build
    count_kernel<<<(E + 255) / 256, 256>>>(ei, E, N);
    scan_kernel<<<1, 1024>>>(N);
    fill_kernel<<<(E + 255) / 256, 256>>>(ei, E, N);

    int mblocks = (N + BMt - 1) / BMt;    // 157

    // Layer 1
    mma_gemm_kernel<<<dim3(DH / BNt, mblocks), 256>>>(0, nullptr, nullptr, DH);
    agg_kernel<<<N, 128>>>(b1, 1);

    // Layer 2
    mma_gemm_kernel<<<dim3(DH / BNt, mblocks), 256>>>(1, nullptr, nullptr, DH);
    agg_kernel<<<N, 128>>>(b2, 0);

    // Classifier
    mma_gemm_kernel<<<dim3(1, mblocks), 256>>>(2, bc, out, d_out_dim);
}